// round 15
// baseline (speedup 1.0000x reference)
#include <cuda_runtime.h>
#include <math.h>

// Fixed problem shapes (B=256, R=512, D=64, N=100000, E=3.2M)
#define RR   512
#define DD   64
#define BB   256
#define NN   100000
#define NBW  3136         // bitmap words: ceil(100000/32)=3125, padded
#define DIN  132          // 2*DD + 4
#define TBL  1024         // hash table slots (load factor <= 0.25)
#define TBLM (TBL - 1)
#define EMPTY_KEY (-1)
#define EGRID 592         // edge blocks: 4 per SM
#define GC   4            // gather chunks per b (grid.y)

// Scratch. g_scratch = [Mq: BB*RR][relc: RR][deg: BB] -> ONE memset node.
// g_rep / g_part are fully overwritten every launch -> no clearing needed.
__device__ int   g_scratch[BB * RR + RR + BB];
__device__ int   g_rep[BB];
__device__ float g_part[BB * GC * DD];

__device__ __forceinline__ unsigned hash_ent(int x) {
    return ((unsigned)x * 2654435761u) >> 16;
}

// ---------------------------------------------------------------- edge scan
// Fast path: SMEM membership bitmap (1 LDS + bit test per endpoint).
// Slow path (rare): bounded SMEM hash probe -> global atomic into Mq.
// Block 0 additionally resolves g_rep[b] from its hash (min-b dedup).
__device__ __forceinline__ void lookup_add(int e, int y,
                                           const int* __restrict__ skeys,
                                           const int* __restrict__ svals) {
    unsigned s = hash_ent(e) & TBLM;
    #pragma unroll 1
    for (int p = 0; p < TBL; p++) {
        int k = skeys[s];
        if (k == e) { atomicAdd(&g_scratch[svals[s] * RR + y], 1); return; }
        if (k == EMPTY_KEY) return;
        s = (s + 1) & TBLM;
    }
}

__device__ __forceinline__ void process_edge(int h, int t, int y,
                                             const unsigned* __restrict__ sbit,
                                             const int* __restrict__ skeys,
                                             const int* __restrict__ svals,
                                             int* __restrict__ shist) {
    atomicAdd(&shist[y], 1);
    bool hh = (sbit[h >> 5] >> (h & 31)) & 1u;
    bool ht = ((sbit[t >> 5] >> (t & 31)) & 1u) && (t != h);  // self-loop once
    if (hh | ht) {                          // rare
        if (hh) lookup_add(h, y, skeys, svals);
        if (ht) lookup_add(t, y, skeys, svals);
    }
}

__global__ __launch_bounds__(256) void k_edges(const int* __restrict__ heads,
                                               const int* __restrict__ tails,
                                               const int* __restrict__ types,
                                               const int* __restrict__ qent,
                                               int B, int E) {
    __shared__ unsigned sbit[NBW];          // 12.25 KB membership bitmap
    __shared__ int skeys[TBL];              // 4 KB
    __shared__ int svals[TBL];              // 4 KB
    __shared__ int shist[RR];               // 2 KB
    int tid = threadIdx.x;
    for (int j = tid; j < NBW; j += 256) sbit[j] = 0u;
    for (int j = tid; j < TBL; j += 256) { skeys[j] = EMPTY_KEY; svals[j] = 0x7FFFFFFF; }
    for (int j = tid; j < RR; j += 256) shist[j] = 0;
    __syncthreads();
    // build bitmap + hash from qent (dedup via min-b); bounded probes
    for (int q = tid; q < B; q += 256) {
        int ent = qent[q];
        atomicOr(&sbit[ent >> 5], 1u << (ent & 31));
        unsigned s = hash_ent(ent) & TBLM;
        #pragma unroll 1
        for (int p = 0; p < TBL; p++) {
            int prev = atomicCAS(&skeys[s], EMPTY_KEY, ent);
            if (prev == EMPTY_KEY || prev == ent) {
                atomicMin(&svals[s], q);    // representative = min b
                break;
            }
            s = (s + 1) & TBLM;
        }
    }
    __syncthreads();
    // block 0: publish rep[b] for the epilogue kernels (bounded probes)
    if (blockIdx.x == 0) {
        for (int q = tid; q < B; q += 256) {
            int ent = qent[q];
            unsigned s = hash_ent(ent) & TBLM;
            int rep = q;
            #pragma unroll 1
            for (int p = 0; p < TBL; p++) {
                if (skeys[s] == ent) { rep = svals[s]; break; }
                s = (s + 1) & TBLM;
            }
            g_rep[q] = rep;
        }
    }

    const int4* h4 = (const int4*)heads;
    const int4* t4 = (const int4*)tails;
    const int4* y4 = (const int4*)types;
    int E4 = E >> 2;
    int gid = blockIdx.x * blockDim.x + tid;
    int stride = gridDim.x * blockDim.x;
    for (int i = gid; i < E4; i += stride) {
        int4 h = h4[i];
        int4 t = t4[i];
        int4 y = y4[i];
        process_edge(h.x, t.x, y.x, sbit, skeys, svals, shist);
        process_edge(h.y, t.y, y.y, sbit, skeys, svals, shist);
        process_edge(h.z, t.z, y.z, sbit, skeys, svals, shist);
        process_edge(h.w, t.w, y.w, sbit, skeys, svals, shist);
    }
    if (blockIdx.x == 0 && tid < (E & 3)) {
        int e = (E4 << 2) + tid;
        process_edge(heads[e], tails[e], types[e], sbit, skeys, svals, shist);
    }
    __syncthreads();
    int* relc = g_scratch + BB * RR;
    for (int j = tid; j < RR; j += 256) {
        int v = shist[j];
        if (v) atomicAdd(&relc[j], v);
    }
}

// ---------------------------------------------------------------- gather
// grid (B, GC), 256 threads. Block (b, c) sums its 128-relation quarter of
// the masked mean: 4 sub-groups of 64 d-threads, 32 relations each.
// 1024 blocks -> ~7/SM: latency chains overlap chip-wide.
__global__ __launch_bounds__(256) void k_gather(const float* __restrict__ rel_emb) {
    int b = blockIdx.x;
    int c = blockIdx.y;
    int tid = threadIdx.x;
    int lane = tid & 31;
    __shared__ float scnt[128];
    __shared__ float spart[4 * DD];

    int rep = g_rep[b];                     // uniform load
    int* deg = g_scratch + BB * RR + RR;
    if (tid < 128) {
        int cc = g_scratch[rep * RR + c * 128 + tid];
        scnt[tid] = (float)cc;
        #pragma unroll
        for (int o = 16; o; o >>= 1) cc += __shfl_down_sync(0xffffffffu, cc, o);
        if (lane == 0) atomicAdd(&deg[b], cc);   // integer: deterministic
    }
    __syncthreads();

    int d = tid & 63;
    int sub = tid >> 6;                     // 0..3, relations [sub*32, sub*32+32)
    const float* base = rel_emb + (size_t)b * RR * DD + (size_t)(c * 128) * DD + d;
    float acc = 0.f;
    #pragma unroll
    for (int j = 0; j < 32; j++) {
        int r = sub * 32 + j;
        float cw = scnt[r];                 // uniform across the 64-thread group
        if (cw != 0.0f) acc = fmaf(cw, base[(size_t)r * DD], acc);
    }
    spart[sub * DD + d] = acc;
    __syncthreads();
    if (tid < DD) {
        float s = (spart[tid] + spart[64 + tid])
                + (spart[128 + tid] + spart[192 + tid]);   // fixed order
        g_part[((size_t)b * GC + c) * DD + tid] = s;
    }
}

// ---------------------------------------------------------------- mlp
// grid B, 256 threads: fixed-order partial combine + stats + MLP.
__global__ __launch_bounds__(256) void k_mlp(
    const float* __restrict__ rel_emb,
    const int* __restrict__ qrels,
    const float* __restrict__ W1, const float* __restrict__ b1,
    const float* __restrict__ W2, const float* __restrict__ b2,
    const float* __restrict__ W3, const float* __restrict__ b3,
    const float* __restrict__ W4, const float* __restrict__ b4,
    float* __restrict__ out, int E, float density) {
    int b = blockIdx.x;
    int tid = threadIdx.x;
    __shared__ float sx[DIN];
    __shared__ float sw[4][DD];
    __shared__ float sh1[DD];
    __shared__ float sh2[32];
    __shared__ float sg[16];

    const int* deg_arr = g_scratch + BB * RR + RR;
    const int* relc = g_scratch + BB * RR;
    float deg = (float)deg_arr[b];
    float inv = 1.0f / fmaxf(deg, 1.0f);
    int qr = qrels[b];

    if (tid < DD) {
        const float* p = g_part + (size_t)b * GC * DD + tid;
        float s = (p[0] + p[DD]) + (p[2 * DD] + p[3 * DD]);   // fixed order
        sx[DD + tid] = s * inv;
        sx[tid] = rel_emb[((size_t)b * RR + qr) * DD + tid];
    }
    if (tid == 0) {
        float freq = fminf((float)relc[qr] / (float)E, 1.0f);
        float degn = fminf(deg / (float)E, 1.0f);
        sx[128] = freq;
        sx[129] = degn;
        sx[130] = freq;
        sx[131] = density;
    }
    __syncthreads();

    // W1: 132 -> 64, input range split across 4 groups of 33, 256 threads
    {
        int o = tid & 63;
        int h = tid >> 6;           // 0..3, inputs [h*33, h*33+33)
        int i0 = h * 33;
        float a0 = 0.f, a1 = 0.f, a2 = 0.f, a3 = 0.f;
        const float* wcol = W1 + o;
        #pragma unroll
        for (int i = 0; i < 32; i += 4) {
            a0 = fmaf(sx[i0 + i],     wcol[(i0 + i) * 64],     a0);
            a1 = fmaf(sx[i0 + i + 1], wcol[(i0 + i + 1) * 64], a1);
            a2 = fmaf(sx[i0 + i + 2], wcol[(i0 + i + 2) * 64], a2);
            a3 = fmaf(sx[i0 + i + 3], wcol[(i0 + i + 3) * 64], a3);
        }
        a0 = fmaf(sx[i0 + 32], wcol[(i0 + 32) * 64], a0);
        sw[h][o] = (a0 + a1) + (a2 + a3);
    }
    __syncthreads();
    if (tid < DD)
        sh1[tid] = fmaxf(b1[tid] + (sw[0][tid] + sw[1][tid])
                                 + (sw[2][tid] + sw[3][tid]), 0.0f);
    __syncthreads();
    if (tid < 32) {
        float a0 = b2[tid], a1 = 0.f, a2 = 0.f, a3 = 0.f;
        #pragma unroll
        for (int i = 0; i < 64; i += 4) {
            a0 = fmaf(sh1[i],     W2[i * 32 + tid],       a0);
            a1 = fmaf(sh1[i + 1], W2[(i + 1) * 32 + tid], a1);
            a2 = fmaf(sh1[i + 2], W2[(i + 2) * 32 + tid], a2);
            a3 = fmaf(sh1[i + 3], W2[(i + 3) * 32 + tid], a3);
        }
        sh2[tid] = fmaxf((a0 + a1) + (a2 + a3), 0.0f);
    }
    __syncthreads();
    if (tid < 16) {
        float a0 = b3[tid], a1 = 0.f;
        #pragma unroll
        for (int i = 0; i < 32; i += 2) {
            a0 = fmaf(sh2[i],     W3[i * 16 + tid],       a0);
            a1 = fmaf(sh2[i + 1], W3[(i + 1) * 16 + tid], a1);
        }
        sg[tid] = fmaxf(a0 + a1, 0.0f);
    }
    __syncthreads();
    if (tid == 0) {
        float acc = b4[0];
        #pragma unroll
        for (int i = 0; i < 16; i++) acc = fmaf(sg[i], W4[i], acc);
        out[b] = 1.0f / (1.0f + expf(-acc));
    }
}

// ---------------------------------------------------------------- launch
extern "C" void kernel_launch(void* const* d_in, const int* in_sizes, int n_in,
                              void* d_out, int out_size) {
    const float* rel_emb = (const float*)d_in[0];
    const int*   qrels   = (const int*)d_in[1];
    const int*   qent    = (const int*)d_in[2];
    const int*   eidx    = (const int*)d_in[3];
    const int*   etype   = (const int*)d_in[4];
    const float* W1 = (const float*)d_in[n_in - 8];
    const float* b1 = (const float*)d_in[n_in - 7];
    const float* W2 = (const float*)d_in[n_in - 6];
    const float* b2 = (const float*)d_in[n_in - 5];
    const float* W3 = (const float*)d_in[n_in - 4];
    const float* b3 = (const float*)d_in[n_in - 3];
    const float* W4 = (const float*)d_in[n_in - 2];
    const float* b4 = (const float*)d_in[n_in - 1];

    int B = in_sizes[1];          // 256
    int E = in_sizes[4];          // 3,200,000
    const int* heads = eidx;
    const int* tails = eidx + E;

    double Nd = (double)NN;       // fixed problem
    float density = (float)fmin((double)E / (Nd * Nd), 1.0);

    // single clear node for Mq + relc + deg
    void* pS = nullptr;
    cudaGetSymbolAddress(&pS, g_scratch);
    cudaMemsetAsync(pS, 0, (BB * RR + RR + BB) * sizeof(int));

    k_edges<<<EGRID, 256>>>(heads, tails, etype, qent, B, E);
    k_gather<<<dim3(BB, GC), 256>>>(rel_emb);
    k_mlp<<<BB, 256>>>(rel_emb, qrels,
                       W1, b1, W2, b2, W3, b3, W4, b4,
                       (float*)d_out, E, density);
}